// round 13
// baseline (speedup 1.0000x reference)
#include <cuda_runtime.h>
#include <cuda_bf16.h>
#include <math.h>

// Election hash table: 2^21 slots x 8B = 16MB.
// word = (cell+1) << 23 | (pair+1) << 3 | bucket ; 0 = empty.
//   cell+1  <= 2^26  (fits in bits [23,50))
//   (pair+1)<<3 | bucket < 2^23
// Within a cell, word order == pair order -> CAS-max = last pair wins.
// Self-cleaned by the sweep's SM stores (keeps table L2-hot for the next
// replay's elect — proven R10 vs R11).
#define TBL_BITS 21
#define TBL_SIZE (1u << TBL_BITS)
#define TBL_MASK (TBL_SIZE - 1u)
__device__ unsigned long long g_tbl[TBL_SIZE];

// Resolve one pair's election given the result of its first (blind) CAS.
__device__ __forceinline__ void resolve(unsigned h, unsigned long long cid,
                                        unsigned long long mine,
                                        unsigned long long old,
                                        unsigned long long expected) {
    for (;;) {
        if (old == expected) return;             // installed
        if ((old >> 23) == cid) {                // my cell owns this slot
            if (old >= mine) return;             // later pair already won
            expected = old;                      // retry same slot
        } else {                                 // other cell: next slot
            h = (h + 1u) & TBL_MASK;
            expected = 0ull;
        }
        old = atomicCAS(&g_tbl[h], expected, mine);
    }
}

// Pass A: election. int4 input loads (3 coalesced loads / 4 pairs), then the
// FOUR first CASes issued back-to-back (independent -> 4 overlapped L2 round
// trips) before any resolution.
__global__ void se_elect(const int4* __restrict__ src4,
                         const int4* __restrict__ dst4,
                         const int4* __restrict__ path_len4,
                         int n_quads, int n_pairs, int nn, int max_path) {
    int q = blockIdx.x * blockDim.x + threadIdx.x;
    if (q >= n_quads) return;

    int4 s4 = __ldg(&src4[q]);
    int4 d4 = __ldg(&dst4[q]);
    int4 p4 = __ldg(&path_len4[q]);

    int i0 = q * 4;
    int sv[4] = {s4.x, s4.y, s4.z, s4.w};
    int dv[4] = {d4.x, d4.y, d4.z, d4.w};
    int pv[4] = {p4.x, p4.y, p4.z, p4.w};

    unsigned h[4];
    unsigned long long cid[4], mine[4], old[4];
    bool act[4];

#pragma unroll
    for (int k = 0; k < 4; k++) {
        int i = i0 + k;
        act[k] = (i < n_pairs);
        if (act[k]) {
            int bu = (pv[k] < max_path ? pv[k] : max_path) - 1;
            if (bu < 0) bu = 0;
            unsigned cell = (unsigned)sv[k] * (unsigned)nn + (unsigned)dv[k];
            cid[k]  = (unsigned long long)(cell + 1u);
            mine[k] = (cid[k] << 23) |
                      ((unsigned long long)(unsigned)(i + 1) << 3) |
                      (unsigned long long)bu;
            h[k] = (cell * 2654435761u) & TBL_MASK;
        }
    }
    // 4 independent blind CASes in flight
#pragma unroll
    for (int k = 0; k < 4; k++)
        if (act[k]) old[k] = atomicCAS(&g_tbl[h[k]], 0ull, mine[k]);
    // resolve (fast path: old==0 -> installed, no further atomics)
#pragma unroll
    for (int k = 0; k < 4; k++)
        if (act[k]) resolve(h[k], cid[k], mine[k], old[k], 0ull);
}

// Pass B: coalesced table sweep; winners stored with __stwt (write-through,
// no-allocate -> no random sector-fill reads). Self-clean with plain SM
// stores (keeps table lines dirty in L2 for next replay's elect).
__global__ void se_sweep(const float* __restrict__ b,
                         float* __restrict__ out_f) {
    unsigned t = blockIdx.x * blockDim.x + threadIdx.x;   // one ull2 / thread
    ulonglong2* p = reinterpret_cast<ulonglong2*>(g_tbl) + t;
    ulonglong2 w = *p;
    if (w.x | w.y) {
        *p = make_ulonglong2(0ull, 0ull);                 // self-clean (L2-warm)
        if (w.x) {
            unsigned cell = (unsigned)(w.x >> 23) - 1u;
            __stwt(&out_f[cell], __ldg(&b[(unsigned)w.x & 7u]));
        }
        if (w.y) {
            unsigned cell = (unsigned)(w.y >> 23) - 1u;
            __stwt(&out_f[cell], __ldg(&b[(unsigned)w.y & 7u]));
        }
    }
}

extern "C" void kernel_launch(void* const* d_in, const int* in_sizes, int n_in,
                              void* d_out, int out_size) {
    // inputs: x [n_nodes,128] f32 (unused), b [max_path] f32,
    //         src [n_pairs] i32, dst [n_pairs] i32, path_len [n_pairs] i32
    const float* b        = (const float*)d_in[1];
    const int*   src      = (const int*)d_in[2];
    const int*   dst      = (const int*)d_in[3];
    const int*   path_len = (const int*)d_in[4];

    int max_path = in_sizes[1];
    int n_pairs  = in_sizes[2];
    int nn = (int)(sqrt((double)out_size) + 0.5);

    const int T = 256;

    // 1) election (table L2-warm from previous replay's sweep self-clean)
    int n_quads = (n_pairs + 3) / 4;
    int blocksA = (n_quads + T - 1) / T;
    se_elect<<<blocksA, T>>>((const int4*)src, (const int4*)dst,
                             (const int4*)path_len,
                             n_quads, n_pairs, nn, max_path);

    // 2) mandatory 256MB zero-fill at CE speed (fastest measured path)
    cudaMemsetAsync(d_out, 0, (size_t)out_size * sizeof(float), 0);

    // 3) sweep: coalesced table read, write-through winner stores, self-clean
    int blocksB = (TBL_SIZE / 2 + T - 1) / T;
    se_sweep<<<blocksB, T>>>(b, (float*)d_out);
}

// round 14
// speedup vs baseline: 1.1929x; 1.1929x over previous
#include <cuda_runtime.h>
#include <cuda_bf16.h>
#include <math.h>

// R0 skeleton, micro-optimized. out itself is the election table:
//   after memset, out[cell] (as int) = 0
//   elect: atomicMax(out_i[cell], packed), packed = (pair+1)<<3 | bucket
//   write: winner (out_i[cell]==packed) overwrites with float b[bucket]
// packed < 2^23 -> positive int, and any cell not yet converted holds either
// 0 or a packed int; winners are unique per cell -> race-free final stores.

#define EPT 4   // pairs per thread, elect (fire-and-forget, no latency chain)
#define WPT 2   // pairs per thread, write (keeps thread count high for MLP)

// Pass 1: election. int4 input loads + independent REDG.MAX per pair.
__global__ void __launch_bounds__(256)
se_elect(const int4* __restrict__ src4,
         const int4* __restrict__ dst4,
         const int4* __restrict__ path_len4,
         int n_quads, int n_pairs, int nn, int max_path,
         int* __restrict__ out_i) {
    int q = blockIdx.x * blockDim.x + threadIdx.x;
    if (q >= n_quads) return;

    int4 s4 = __ldg(&src4[q]);
    int4 d4 = __ldg(&dst4[q]);
    int4 p4 = __ldg(&path_len4[q]);

    int i0 = q * 4;
    int sv[4] = {s4.x, s4.y, s4.z, s4.w};
    int dv[4] = {d4.x, d4.y, d4.z, d4.w};
    int pv[4] = {p4.x, p4.y, p4.z, p4.w};

#pragma unroll
    for (int k = 0; k < 4; k++) {
        int i = i0 + k;
        if (i < n_pairs) {
            int bu = (pv[k] < max_path ? pv[k] : max_path) - 1;
            if (bu < 0) bu = 0;
            unsigned cell = (unsigned)sv[k] * (unsigned)nn + (unsigned)dv[k];
            atomicMax(&out_i[cell], ((i + 1) << 3) | bu);   // fire-and-forget
        }
    }
}

// Pass 2: winners convert packed -> float. WPT independent random reads per
// thread issued back-to-back (overlapped round trips), then compares+stores.
// Reads hit lines elect just dirtied (L2-resident portion).
__global__ void __launch_bounds__(256)
se_write(const float* __restrict__ b,
         const int* __restrict__ src,
         const int* __restrict__ dst,
         const int* __restrict__ path_len,
         int n_pairs, int nn, int max_path,
         int* __restrict__ out_i,
         float* __restrict__ out_f) {
    int tid = blockIdx.x * blockDim.x + threadIdx.x;
    int nth = gridDim.x * blockDim.x;

    unsigned cell[WPT];
    int packed[WPT], bu[WPT], w[WPT];
    bool act[WPT];

#pragma unroll
    for (int k = 0; k < WPT; k++) {
        int i = tid + k * nth;
        act[k] = (i < n_pairs);
        if (act[k]) {
            int pl = __ldg(&path_len[i]);
            int t = (pl < max_path ? pl : max_path) - 1;
            bu[k] = t < 0 ? 0 : t;
            packed[k] = ((i + 1) << 3) | bu[k];
            cell[k] = (unsigned)__ldg(&src[i]) * (unsigned)nn +
                      (unsigned)__ldg(&dst[i]);
        }
    }
    // independent random reads in flight together
#pragma unroll
    for (int k = 0; k < WPT; k++)
        if (act[k]) w[k] = __ldcg(&out_i[cell[k]]);
#pragma unroll
    for (int k = 0; k < WPT; k++)
        if (act[k] && w[k] == packed[k])
            out_f[cell[k]] = __ldg(&b[bu[k]]);
}

extern "C" void kernel_launch(void* const* d_in, const int* in_sizes, int n_in,
                              void* d_out, int out_size) {
    // inputs: x [n_nodes,128] f32 (unused), b [max_path] f32,
    //         src [n_pairs] i32, dst [n_pairs] i32, path_len [n_pairs] i32
    const float* b        = (const float*)d_in[1];
    const int*   src      = (const int*)d_in[2];
    const int*   dst      = (const int*)d_in[3];
    const int*   path_len = (const int*)d_in[4];

    int max_path = in_sizes[1];
    int n_pairs  = in_sizes[2];
    int nn = (int)(sqrt((double)out_size) + 0.5);

    int*   out_i = (int*)d_out;
    float* out_f = (float*)d_out;

    const int T = 256;

    // 1) mandatory 256MB zero-fill at CE speed (also zeroes the elect table)
    cudaMemsetAsync(d_out, 0, (size_t)out_size * sizeof(float), 0);

    // 2) election: vectorized loads + fire-and-forget REDG.MAX
    int n_quads = (n_pairs + 3) / 4;
    int blocksA = (n_quads + T - 1) / T;
    se_elect<<<blocksA, T>>>((const int4*)src, (const int4*)dst,
                             (const int4*)path_len,
                             n_quads, n_pairs, nn, max_path, out_i);

    // 3) winners convert packed -> float (reads hit elect's dirty L2 lines)
    int blocksB = (n_pairs + T * WPT - 1) / (T * WPT);
    se_write<<<blocksB, T>>>(b, src, dst, path_len,
                             n_pairs, nn, max_path, out_i, out_f);
}